// round 5
// baseline (speedup 1.0000x reference)
#include <cuda_runtime.h>

#define BATCH 128
#define CH 256
#define HW 3136          // 56*56
#define PFD 8            // per-filter dim
#define KDIM 2048        // CH*PFD
#define JH 256           // final hidden
#define NCLS 1000
#define KSPLIT 16        // k-splits for gemm2
#define JTILES 8         // 256/32

// Scratch (allocation-free rule: __device__ globals)
__device__ float g_concat[BATCH * KDIM];            // 1 MB
__device__ float g_hpart[KSPLIT * BATCH * JH];      // 2 MB, deterministic split-K partials
__device__ float g_h[BATCH * JH];                   // 128 KB, reduced+bias+relu hidden

// ---------------------------------------------------------------------------
// Kernel 1: global average pool fused with per-channel Linear(1->8)+ReLU.
// One warp per (b,c) pair; 8 front-batched float4 LDGs per chunk (MLP=8).
// ---------------------------------------------------------------------------
__global__ void __launch_bounds__(512) pool_kernel(const float* __restrict__ x,
                                                   const float* __restrict__ W1,
                                                   const float* __restrict__ b1) {
    int warp = threadIdx.x >> 5;
    int lane = threadIdx.x & 31;
    int pair = blockIdx.x * 16 + warp;       // pair = b*CH + c, in [0, 32768)
    const float4* xv = (const float4*)(x + (long)pair * HW);

    float s0 = 0.f, s1 = 0.f, s2 = 0.f, s3 = 0.f;
    // 784 float4 per pair = 3 chunks of 8x32 + tail of 16
    #pragma unroll
    for (int c = 0; c < 3; c++) {
        float4 v[8];
        #pragma unroll
        for (int u = 0; u < 8; u++)
            v[u] = xv[lane + 32 * u + 256 * c];
        #pragma unroll
        for (int u = 0; u < 8; u += 4) {
            s0 += v[u].x + v[u].y;         s1 += v[u].z + v[u].w;
            s2 += v[u+1].x + v[u+1].y;     s3 += v[u+1].z + v[u+1].w;
            s0 += v[u+2].x + v[u+2].y;     s1 += v[u+2].z + v[u+2].w;
            s2 += v[u+3].x + v[u+3].y;     s3 += v[u+3].z + v[u+3].w;
        }
    }
    if (lane < 16) {
        float4 v = xv[768 + lane];
        s0 += v.x + v.y; s1 += v.z + v.w;
    }
    float s = (s0 + s1) + (s2 + s3);
    #pragma unroll
    for (int off = 16; off; off >>= 1)
        s += __shfl_xor_sync(0xffffffffu, s, off);

    float p = s * (1.0f / 3136.0f);          // mean, present in all lanes
    int b = pair >> 8;
    int c = pair & 255;
    if (lane < PFD) {
        float v = fmaf(p, W1[c * PFD + lane], b1[c * PFD + lane]);
        g_concat[b * KDIM + c * PFD + lane] = fmaxf(v, 0.f);
    }
}

// ---------------------------------------------------------------------------
// Kernel 2: h_partial[ks][b][j] = sum_{k in slice ks} concat[b][k] * W2[j][k]
// 128 blocks, [128b x 32j] tile per K-slice of 128. 4x4 register blocking.
// ---------------------------------------------------------------------------
__global__ void __launch_bounds__(256) gemm2_kernel(const float* __restrict__ W2) {
    __shared__ float cs[BATCH * 68];   // concat tile [128][64] (stride 68)
    __shared__ float ws[32 * 68];      // W2 tile     [32][64]  (stride 68)

    int jt = blockIdx.x & 7;           // j-tile
    int ks = blockIdx.x >> 3;          // k-split
    int j0 = jt * 32;
    int t = threadIdx.x;
    int jgrp  = t & 7;                 // j = j0 + jgrp + 8*jjj
    int bbase = t >> 3;                // b = bbase + 32*bi

    float acc[4][4];
    #pragma unroll
    for (int a = 0; a < 4; a++)
        #pragma unroll
        for (int b = 0; b < 4; b++) acc[a][b] = 0.f;

    #pragma unroll
    for (int kt = 0; kt < 2; kt++) {
        int kb = ks * 128 + kt * 64;

        #pragma unroll
        for (int i = 0; i < 8; i++) {
            int f = t + 256 * i;
            int bb = f >> 4, kq = f & 15;
            float4 v = *(const float4*)(g_concat + bb * KDIM + kb + kq * 4);
            *(float4*)(cs + bb * 68 + kq * 4) = v;
        }
        #pragma unroll
        for (int i = 0; i < 2; i++) {
            int f = t + 256 * i;
            int jj = f >> 4, kq = f & 15;
            float4 v = *(const float4*)(W2 + (long)(j0 + jj) * KDIM + kb + kq * 4);
            *(float4*)(ws + jj * 68 + kq * 4) = v;
        }
        __syncthreads();

        #pragma unroll 4
        for (int k = 0; k < 64; k++) {
            float wv[4], cv[4];
            #pragma unroll
            for (int jjj = 0; jjj < 4; jjj++) wv[jjj] = ws[(jgrp + 8 * jjj) * 68 + k];
            #pragma unroll
            for (int bi = 0; bi < 4; bi++)    cv[bi] = cs[(bbase + 32 * bi) * 68 + k];
            #pragma unroll
            for (int jjj = 0; jjj < 4; jjj++)
                #pragma unroll
                for (int bi = 0; bi < 4; bi++)
                    acc[jjj][bi] = fmaf(wv[jjj], cv[bi], acc[jjj][bi]);
        }
        __syncthreads();
    }

    #pragma unroll
    for (int jjj = 0; jjj < 4; jjj++) {
        int j = j0 + jgrp + 8 * jjj;
        #pragma unroll
        for (int bi = 0; bi < 4; bi++) {
            int b = bbase + 32 * bi;
            g_hpart[(ks * BATCH + b) * JH + j] = acc[jjj][bi];
        }
    }
}

// ---------------------------------------------------------------------------
// Kernel 2.5: g_h[b][j] = relu(b2[j] + sum_ks hpart[ks][b][j]).  One pass.
// ---------------------------------------------------------------------------
__global__ void __launch_bounds__(256) reduceh_kernel(const float* __restrict__ b2) {
    int lin = blockIdx.x * 256 + threadIdx.x;   // 32768 elements
    int j = lin & 255;
    float v = b2[j];
    #pragma unroll
    for (int ks = 0; ks < KSPLIT; ks++)
        v += g_hpart[ks * (BATCH * JH) + lin];
    g_h[lin] = fmaxf(v, 0.f);
}

// ---------------------------------------------------------------------------
// Kernel 3 v3: out[b][n] = sum_j g_h[b][j] * W3[n][j] + b3[n]
// Block = [64b x 16n], 128 threads (4 warps). Warp w owns n = n0+4w+q (q<4),
// lanes span 32 b, bi in {0,1}. W3 comes via WARP-UNIFORM float4 LDG
// (broadcast, no smem crossbar); only h goes through smem (stride 65,
// bank = lane+j -> conflict-free). 1 B smem / FMA -> FMA-issue bound.
// Grid = 63 n-tiles x 2 b-groups = 126 blocks (one full wave).
// ---------------------------------------------------------------------------
__global__ void __launch_bounds__(128) gemm3_kernel(const float* __restrict__ W3,
                                                    const float* __restrict__ b3,
                                                    float* __restrict__ out) {
    __shared__ float hs[64 * 65];      // h tile [64b][64j], stride 65

    int b0 = (blockIdx.x & 1) * 64;
    int n0 = (blockIdx.x >> 1) * 16;   // 0..992
    int t = threadIdx.x;
    int lane = t & 31;
    int w = t >> 5;                    // warp 0..3

    // The 4 n-rows this warp owns (uniform across the warp).
    int nrow[4];
    bool nvalid[4];
    const float* wptr[4];
    #pragma unroll
    for (int q = 0; q < 4; q++) {
        nrow[q] = n0 + w * 4 + q;
        nvalid[q] = nrow[q] < NCLS;
        wptr[q] = W3 + (long)(nvalid[q] ? nrow[q] : 0) * JH;
    }

    float acc[4][2];
    #pragma unroll
    for (int q = 0; q < 4; q++) { acc[q][0] = 0.f; acc[q][1] = 0.f; }

    #pragma unroll
    for (int jt = 0; jt < 4; jt++) {
        // Stage h chunk [64b][64j]: 1024 float4 reads, 8 per thread, coalesced.
        #pragma unroll
        for (int i = 0; i < 8; i++) {
            int f = t + 128 * i;       // 0..1023
            int bb = f >> 4;           // 0..63
            int k4 = f & 15;           // j quad
            float4 v = *(const float4*)(g_h + (b0 + bb) * JH + jt * 64 + k4 * 4);
            float* hp = hs + bb * 65 + k4 * 4;
            hp[0] = v.x; hp[1] = v.y; hp[2] = v.z; hp[3] = v.w;
        }
        __syncthreads();

        #pragma unroll 2
        for (int j4 = 0; j4 < 16; j4++) {
            // Warp-uniform W3 loads: one float4 per owned n (broadcast LDG).
            float4 wq[4];
            #pragma unroll
            for (int q = 0; q < 4; q++)
                wq[q] = *(const float4*)(wptr[q] + jt * 64 + j4 * 4);

            #pragma unroll
            for (int jj = 0; jj < 4; jj++) {
                int j = j4 * 4 + jj;
                float h0 = hs[lane * 65 + j];
                float h1 = hs[(32 + lane) * 65 + j];
                #pragma unroll
                for (int q = 0; q < 4; q++) {
                    float wv = (jj == 0) ? wq[q].x : (jj == 1) ? wq[q].y
                             : (jj == 2) ? wq[q].z : wq[q].w;
                    acc[q][0] = fmaf(wv, h0, acc[q][0]);
                    acc[q][1] = fmaf(wv, h1, acc[q][1]);
                }
            }
        }
        __syncthreads();
    }

    #pragma unroll
    for (int q = 0; q < 4; q++) {
        if (nvalid[q]) {
            float bn = b3[nrow[q]];
            out[(long)(b0 + lane) * NCLS + nrow[q]]      = acc[q][0] + bn;
            out[(long)(b0 + 32 + lane) * NCLS + nrow[q]] = acc[q][1] + bn;
        }
    }
}

// ---------------------------------------------------------------------------
extern "C" void kernel_launch(void* const* d_in, const int* in_sizes, int n_in,
                              void* d_out, int out_size) {
    const float* x  = (const float*)d_in[0];
    const float* W1 = (const float*)d_in[1];
    const float* b1 = (const float*)d_in[2];
    const float* W2 = (const float*)d_in[3];
    const float* b2 = (const float*)d_in[4];
    const float* W3 = (const float*)d_in[5];
    const float* b3 = (const float*)d_in[6];
    float* out = (float*)d_out;

    pool_kernel<<<(BATCH * CH) / 16, 512>>>(x, W1, b1);       // 2048 blocks
    gemm2_kernel<<<KSPLIT * JTILES, 256>>>(W2);               // 128 blocks
    reduceh_kernel<<<(BATCH * JH) / 256, 256>>>(b2);          // 128 blocks
    gemm3_kernel<<<126, 128>>>(W3, b3, out);                  // 63 n-tiles x 2 b
}

// round 6
// speedup vs baseline: 1.0729x; 1.0729x over previous
#include <cuda_runtime.h>

#define BATCH 128
#define CH 256
#define HW 3136          // 56*56
#define PFD 8            // per-filter dim
#define KDIM 2048        // CH*PFD
#define JH 256           // final hidden
#define NCLS 1000
#define KSPLIT 16        // k-splits for gemm2
#define JTILES 8         // 256/32

// Scratch (allocation-free rule: __device__ globals)
__device__ float g_concat[BATCH * KDIM];            // 1 MB
__device__ float g_hpart[KSPLIT * BATCH * JH];      // 2 MB, deterministic split-K partials
__device__ float g_h[BATCH * JH];                   // 128 KB, reduced+bias+relu hidden

// ---------------------------------------------------------------------------
// Kernel 1: global average pool fused with per-channel Linear(1->8)+ReLU.
// One warp per (b,c) pair; 8 front-batched float4 LDGs per chunk (MLP=8).
// ---------------------------------------------------------------------------
__global__ void __launch_bounds__(512) pool_kernel(const float* __restrict__ x,
                                                   const float* __restrict__ W1,
                                                   const float* __restrict__ b1) {
    int warp = threadIdx.x >> 5;
    int lane = threadIdx.x & 31;
    int pair = blockIdx.x * 16 + warp;       // pair = b*CH + c, in [0, 32768)
    const float4* xv = (const float4*)(x + (long)pair * HW);

    float s0 = 0.f, s1 = 0.f, s2 = 0.f, s3 = 0.f;
    // 784 float4 per pair = 3 chunks of 8x32 + tail of 16
    #pragma unroll
    for (int c = 0; c < 3; c++) {
        float4 v[8];
        #pragma unroll
        for (int u = 0; u < 8; u++)
            v[u] = xv[lane + 32 * u + 256 * c];
        #pragma unroll
        for (int u = 0; u < 8; u += 4) {
            s0 += v[u].x + v[u].y;         s1 += v[u].z + v[u].w;
            s2 += v[u+1].x + v[u+1].y;     s3 += v[u+1].z + v[u+1].w;
            s0 += v[u+2].x + v[u+2].y;     s1 += v[u+2].z + v[u+2].w;
            s2 += v[u+3].x + v[u+3].y;     s3 += v[u+3].z + v[u+3].w;
        }
    }
    if (lane < 16) {
        float4 v = xv[768 + lane];
        s0 += v.x + v.y; s1 += v.z + v.w;
    }
    float s = (s0 + s1) + (s2 + s3);
    #pragma unroll
    for (int off = 16; off; off >>= 1)
        s += __shfl_xor_sync(0xffffffffu, s, off);

    float p = s * (1.0f / 3136.0f);          // mean, present in all lanes
    int b = pair >> 8;
    int c = pair & 255;
    if (lane < PFD) {
        float v = fmaf(p, W1[c * PFD + lane], b1[c * PFD + lane]);
        g_concat[b * KDIM + c * PFD + lane] = fmaxf(v, 0.f);
    }
}

// ---------------------------------------------------------------------------
// Kernel 2: h_partial[ks][b][j] = sum_{k in slice ks} concat[b][k] * W2[j][k]
// 128 blocks, [128b x 32j] tile per K-slice of 128. 4x4 register blocking.
// ---------------------------------------------------------------------------
__global__ void __launch_bounds__(256) gemm2_kernel(const float* __restrict__ W2) {
    __shared__ float cs[BATCH * 68];   // concat tile [128][64] (stride 68)
    __shared__ float ws[32 * 68];      // W2 tile     [32][64]  (stride 68)

    int jt = blockIdx.x & 7;           // j-tile
    int ks = blockIdx.x >> 3;          // k-split
    int j0 = jt * 32;
    int t = threadIdx.x;
    int jgrp  = t & 7;                 // j = j0 + jgrp + 8*jjj
    int bbase = t >> 3;                // b = bbase + 32*bi

    float acc[4][4];
    #pragma unroll
    for (int a = 0; a < 4; a++)
        #pragma unroll
        for (int b = 0; b < 4; b++) acc[a][b] = 0.f;

    #pragma unroll
    for (int kt = 0; kt < 2; kt++) {
        int kb = ks * 128 + kt * 64;

        #pragma unroll
        for (int i = 0; i < 8; i++) {
            int f = t + 256 * i;
            int bb = f >> 4, kq = f & 15;
            float4 v = *(const float4*)(g_concat + bb * KDIM + kb + kq * 4);
            *(float4*)(cs + bb * 68 + kq * 4) = v;
        }
        #pragma unroll
        for (int i = 0; i < 2; i++) {
            int f = t + 256 * i;
            int jj = f >> 4, kq = f & 15;
            float4 v = *(const float4*)(W2 + (long)(j0 + jj) * KDIM + kb + kq * 4);
            *(float4*)(ws + jj * 68 + kq * 4) = v;
        }
        __syncthreads();

        #pragma unroll 4
        for (int k = 0; k < 64; k++) {
            float wv[4], cv[4];
            #pragma unroll
            for (int jjj = 0; jjj < 4; jjj++) wv[jjj] = ws[(jgrp + 8 * jjj) * 68 + k];
            #pragma unroll
            for (int bi = 0; bi < 4; bi++)    cv[bi] = cs[(bbase + 32 * bi) * 68 + k];
            #pragma unroll
            for (int jjj = 0; jjj < 4; jjj++)
                #pragma unroll
                for (int bi = 0; bi < 4; bi++)
                    acc[jjj][bi] = fmaf(wv[jjj], cv[bi], acc[jjj][bi]);
        }
        __syncthreads();
    }

    #pragma unroll
    for (int jjj = 0; jjj < 4; jjj++) {
        int j = j0 + jgrp + 8 * jjj;
        #pragma unroll
        for (int bi = 0; bi < 4; bi++) {
            int b = bbase + 32 * bi;
            g_hpart[(ks * BATCH + b) * JH + j] = acc[jjj][bi];
        }
    }
}

// ---------------------------------------------------------------------------
// Kernel 2.5: g_h[b][j] = relu(b2[j] + sum_ks hpart[ks][b][j]).  One pass.
// ---------------------------------------------------------------------------
__global__ void __launch_bounds__(256) reduceh_kernel(const float* __restrict__ b2) {
    int lin = blockIdx.x * 256 + threadIdx.x;   // 32768 elements
    int j = lin & 255;
    float v = b2[j];
    #pragma unroll
    for (int ks = 0; ks < KSPLIT; ks++)
        v += g_hpart[ks * (BATCH * JH) + lin];
    g_h[lin] = fmaxf(v, 0.f);
}

// ---------------------------------------------------------------------------
// Kernel 3 v4: out[b][n] = sum_j g_h[b][j] * W3[n][j] + b3[n]
// Block = [32b x 32n], 256 threads = 8 warps (2 per SMSP -> latency hiding).
// Warp w owns 4 n-rows (n0 + 4w + q); lanes span the 32 b.
// Full h slice [32b][256j] staged ONCE in smem (stride 257 -> compute reads
// at bank = lane + j, conflict-free; single sync). W3 via warp-uniform
// float4 LDG, unroll-4 so ptxas batches 16 LDGs (MLP=16); W3 tile 32KB
// -> L1-resident after first touch. Grid = 4 bgroups x 32 ntiles = 128.
// ---------------------------------------------------------------------------
__global__ void __launch_bounds__(256) gemm3_kernel(const float* __restrict__ W3,
                                                    const float* __restrict__ b3,
                                                    float* __restrict__ out) {
    __shared__ float hs[32 * 257];     // [32b][256j], stride 257 (32.9 KB)

    int nt = blockIdx.x & 31;          // n-tile 0..31
    int bg = blockIdx.x >> 5;          // b-group 0..3
    int b0 = bg * 32;
    int n0 = nt * 32;
    int t = threadIdx.x;
    int lane = t & 31;
    int w = t >> 5;                    // warp 0..7

    // Stage h slice: 2048 float4, 8 per thread, coalesced LDG.
    #pragma unroll
    for (int i = 0; i < 8; i++) {
        int f = t + 256 * i;           // 0..2047
        int bb = f >> 6;               // 0..31
        int k4 = f & 63;               // j quad 0..63
        float4 v = *(const float4*)(g_h + (b0 + bb) * JH + k4 * 4);
        float* hp = hs + bb * 257 + k4 * 4;
        hp[0] = v.x; hp[1] = v.y; hp[2] = v.z; hp[3] = v.w;
    }
    __syncthreads();

    // Warp-uniform W3 row pointers for the 4 owned n-rows.
    int nrow[4];
    bool nvalid[4];
    const float* wptr[4];
    #pragma unroll
    for (int q = 0; q < 4; q++) {
        nrow[q] = n0 + w * 4 + q;
        nvalid[q] = nrow[q] < NCLS;
        wptr[q] = W3 + (long)(nvalid[q] ? nrow[q] : 0) * JH;
    }

    float acc[4] = {0.f, 0.f, 0.f, 0.f};
    const float* hrow = hs + lane * 257;

    #pragma unroll 4
    for (int j4 = 0; j4 < 64; j4++) {
        float4 wq[4];
        #pragma unroll
        for (int q = 0; q < 4; q++)
            wq[q] = *(const float4*)(wptr[q] + j4 * 4);

        float h0 = hrow[j4 * 4 + 0];
        float h1 = hrow[j4 * 4 + 1];
        float h2 = hrow[j4 * 4 + 2];
        float h3 = hrow[j4 * 4 + 3];

        #pragma unroll
        for (int q = 0; q < 4; q++) {
            acc[q] = fmaf(wq[q].x, h0, acc[q]);
            acc[q] = fmaf(wq[q].y, h1, acc[q]);
            acc[q] = fmaf(wq[q].z, h2, acc[q]);
            acc[q] = fmaf(wq[q].w, h3, acc[q]);
        }
    }

    #pragma unroll
    for (int q = 0; q < 4; q++) {
        if (nvalid[q])
            out[(long)(b0 + lane) * NCLS + nrow[q]] = acc[q] + b3[nrow[q]];
    }
}

// ---------------------------------------------------------------------------
extern "C" void kernel_launch(void* const* d_in, const int* in_sizes, int n_in,
                              void* d_out, int out_size) {
    const float* x  = (const float*)d_in[0];
    const float* W1 = (const float*)d_in[1];
    const float* b1 = (const float*)d_in[2];
    const float* W2 = (const float*)d_in[3];
    const float* b2 = (const float*)d_in[4];
    const float* W3 = (const float*)d_in[5];
    const float* b3 = (const float*)d_in[6];
    float* out = (float*)d_out;

    pool_kernel<<<(BATCH * CH) / 16, 512>>>(x, W1, b1);       // 2048 blocks
    gemm2_kernel<<<KSPLIT * JTILES, 256>>>(W2);               // 128 blocks
    reduceh_kernel<<<(BATCH * JH) / 256, 256>>>(b2);          // 128 blocks
    gemm3_kernel<<<128, 256>>>(W3, b3, out);                  // 4 bg x 32 nt
}